// round 9
// baseline (speedup 1.0000x reference)
#include <cuda_runtime.h>
#include <math.h>
#include <stdint.h>

#define B_SZ 32768
#define H_SZ 1024
#define C_SZ 10
#define KEEP_SCALE 2.0f
#define LRELU_SLOPE 0.01f

// Scratch (device globals — allocation is forbidden)
__device__ float g_z[(size_t)B_SZ * H_SZ];   // pre-activation
__device__ float g_h[(size_t)B_SZ * H_SZ];   // activation * mask * 2

// ===========================================================================
// Helpers
// ===========================================================================
__device__ __forceinline__ uint32_t smem_u32(const void* p) {
    uint32_t a;
    asm("{ .reg .u64 t; cvta.to.shared.u64 t, %1; cvt.u32.u64 %0, t; }"
        : "=r"(a) : "l"(p));
    return a;
}

__device__ __forceinline__ void cp_async16(uint32_t dst, const void* src, int src_bytes) {
    asm volatile("cp.async.cg.shared.global [%0], [%1], 16, %2;"
                 :: "r"(dst), "l"(src), "r"(src_bytes) : "memory");
}

__device__ __forceinline__ float tanh_fast(float x) {
    float r;
    asm("tanh.approx.f32 %0, %1;" : "=f"(r) : "f"(x));
    return r;
}

__device__ __forceinline__ void mma_tf32(float* d, const uint32_t* a, const uint32_t* b) {
    asm volatile(
        "mma.sync.aligned.m16n8k8.row.col.f32.tf32.tf32.f32 "
        "{%0,%1,%2,%3}, {%4,%5,%6,%7}, {%8,%9}, {%0,%1,%2,%3};"
        : "+f"(d[0]), "+f"(d[1]), "+f"(d[2]), "+f"(d[3])
        : "r"(a[0]), "r"(a[1]), "r"(a[2]), "r"(a[3]), "r"(b[0]), "r"(b[1]));
}

// ===========================================================================
// tf32 mma.sync GEMM: Z[m,n] = sum_k A[m,k]*W[n,k] + bias[n]
// CTA 128x128, BK=32, 128 threads (4 warps 2x2, warp tile 64x64).
// 3-stage cp.async pipeline, 108KB smem -> 2 CTAs/SM (bubble hiding).
// Smem m-major [row][36]; tf32 fed as raw fp32 bits (HW truncates).
// ===========================================================================
#define BM 128
#define BN 128
#define BK 32
#define PAD 36
#define NSTAGE 3
#define STG_FLOATS ((BM + BN) * PAD)            // 9216 floats = 36KB
#define GEMM_SMEM (NSTAGE * STG_FLOATS * 4)     // 110592 bytes

template <int K>
__global__ __launch_bounds__(128, 2)
void gemm_tf32_nt(const float* __restrict__ A, const float* __restrict__ W,
                  const float* __restrict__ bias, float* __restrict__ Z)
{
    constexpr int NK = (K + BK - 1) / BK;

    extern __shared__ __align__(16) float sm[];

    const int tid  = threadIdx.x;
    const int wid  = tid >> 5;
    const int lane = tid & 31;
    const int g    = lane >> 2;   // groupID (0..7)
    const int tig  = lane & 3;    // thread-in-group (0..3)
    const int warpM = (wid & 1) * 64;       // 2 warp-rows
    const int warpN = (wid >> 1) * 64;      // 2 warp-cols
    const int bm = blockIdx.y * BM;
    const int bn = blockIdx.x * BN;

    const float* Ag = A + (size_t)bm * K;
    const float* Wg = W + (size_t)bn * K;

    float acc[4][8][4];
#pragma unroll
    for (int i = 0; i < 4; i++)
#pragma unroll
        for (int j = 0; j < 8; j++)
#pragma unroll
            for (int q = 0; q < 4; q++) acc[i][j][q] = 0.f;

    auto load_stage = [&](int s, int kc) {
        const int k0 = kc * BK;
        float* As = sm + s * STG_FLOATS;
        float* Bs = As + BM * PAD;
        // A: 128 rows x 8 quads(16B) = 1024 granules; B same.
#pragma unroll
        for (int it = 0; it < 8; it++) {
            int idx = tid + it * 128;
            int row = idx >> 3, q = idx & 7;
            int gk  = k0 + q * 4;
            int sb  = (K % BK == 0) ? 16 : ((gk < K) ? 16 : 0);
            int gkc = (K % BK == 0) ? gk : min(gk, K - 4);
            cp_async16(smem_u32(&As[row * PAD + q * 4]),
                       Ag + (size_t)row * K + gkc, sb);
        }
#pragma unroll
        for (int it = 0; it < 8; it++) {
            int idx = tid + it * 128;
            int row = idx >> 3, q = idx & 7;
            int gk  = k0 + q * 4;
            int sb  = (K % BK == 0) ? 16 : ((gk < K) ? 16 : 0);
            int gkc = (K % BK == 0) ? gk : min(gk, K - 4);
            cp_async16(smem_u32(&Bs[row * PAD + q * 4]),
                       Wg + (size_t)row * K + gkc, sb);
        }
    };

    // Prologue: stages 0..NSTAGE-2
#pragma unroll
    for (int s = 0; s < NSTAGE - 1; s++) {
        load_stage(s, s);
        asm volatile("cp.async.commit_group;" ::: "memory");
    }

    int buf = 0;
#pragma unroll 1
    for (int ki = 0; ki < NK; ki++) {
        asm volatile("cp.async.wait_group 1;" ::: "memory");
        __syncthreads();

        const float* As = sm + buf * STG_FLOATS;
        const float* Bs = As + BM * PAD;

#pragma unroll
        for (int ks = 0; ks < 4; ks++) {
            const int kb = 8 * ks + tig;

            uint32_t af[4][4];
#pragma unroll
            for (int i = 0; i < 4; i++) {
                int base = (warpM + 16 * i + g) * PAD + kb;
                af[i][0] = __float_as_uint(As[base]);
                af[i][1] = __float_as_uint(As[base + 8 * PAD]);
                af[i][2] = __float_as_uint(As[base + 4]);
                af[i][3] = __float_as_uint(As[base + 8 * PAD + 4]);
            }
            uint32_t bf[8][2];
#pragma unroll
            for (int j = 0; j < 8; j++) {
                int base = (warpN + 8 * j + g) * PAD + kb;
                bf[j][0] = __float_as_uint(Bs[base]);
                bf[j][1] = __float_as_uint(Bs[base + 4]);
            }
#pragma unroll
            for (int i = 0; i < 4; i++)
#pragma unroll
                for (int j = 0; j < 8; j++)
                    mma_tf32(acc[i][j], af[i], bf[j]);
        }

        const int kn = ki + NSTAGE - 1;
        if (kn < NK) load_stage((buf + NSTAGE - 1) % NSTAGE, kn);
        asm volatile("cp.async.commit_group;" ::: "memory");
        buf = (buf + 1) % NSTAGE;
    }

    // Epilogue: bias + store
#pragma unroll
    for (int i = 0; i < 4; i++) {
        int row0 = bm + warpM + 16 * i + g;
#pragma unroll
        for (int j = 0; j < 8; j++) {
            int col = bn + warpN + 8 * j + 2 * tig;
            float2 bi = *reinterpret_cast<const float2*>(&bias[col]);
            float2 v0 = make_float2(acc[i][j][0] + bi.x, acc[i][j][1] + bi.y);
            float2 v1 = make_float2(acc[i][j][2] + bi.x, acc[i][j][3] + bi.y);
            *reinterpret_cast<float2*>(&Z[(size_t)row0 * H_SZ + col]) = v0;
            *reinterpret_cast<float2*>(&Z[(size_t)(row0 + 8) * H_SZ + col]) = v1;
        }
    }
}

// ===========================================================================
// Mixed activation (switch form), fused mask*2 and mask pass-through write.
// Softmax/softmin WITHOUT max-subtraction (|z| is O(10) here; exp is safe),
// single sum-reduction phase. tanh via tanh.approx.f32.
// ===========================================================================
__global__ __launch_bounds__(256)
void act_kernel(const float* __restrict__ Z, const int* __restrict__ tids,
                const float* __restrict__ mask, float* __restrict__ Hout,
                float* __restrict__ MOut)
{
    const int row  = blockIdx.x;
    const int t    = threadIdx.x;
    const int lane = t & 31, wid = t >> 5;
    const size_t base = (size_t)row * H_SZ;

    float4 z4 = *reinterpret_cast<const float4*>(Z + base + t * 4);
    int4  i4 = *reinterpret_cast<const int4*>(tids + t * 4);
    float zr[4] = {z4.x, z4.y, z4.z, z4.w};
    int   tr[4] = {i4.x, i4.y, i4.z, i4.w};

    float s3 = 0.f, s4 = 0.f;
#pragma unroll
    for (int q = 0; q < 4; q++) {
        if (tr[q] == 3) s3 += __expf(zr[q]);
        if (tr[q] == 4) s4 += __expf(-zr[q]);
    }
#pragma unroll
    for (int off = 16; off; off >>= 1) {
        s3 += __shfl_xor_sync(0xffffffffu, s3, off);
        s4 += __shfl_xor_sync(0xffffffffu, s4, off);
    }
    __shared__ float sC[8], sD[8];
    if (lane == 0) { sC[wid] = s3; sD[wid] = s4; }
    __syncthreads();
    s3 = 0.f; s4 = 0.f;
#pragma unroll
    for (int j = 0; j < 8; j++) { s3 += sC[j]; s4 += sD[j]; }
    float r3 = __frcp_rn(s3), r4 = __frcp_rn(s4);

    float4 mk = *reinterpret_cast<const float4*>(mask + base + t * 4);
    float mv[4] = {mk.x, mk.y, mk.z, mk.w};
    float ov[4];
#pragma unroll
    for (int q = 0; q < 4; q++) {
        float x = zr[q], v;
        switch (tr[q]) {
            case 0:  v = fmaxf(x, 0.f); break;
            case 1:  v = tanh_fast(x); break;
            case 2:  v = __frcp_rn(1.f + __expf(-x)); break;
            case 3:  v = __expf(x) * r3; break;
            case 4:  v = __expf(-x) * r4; break;
            case 5:  v = x * normcdff(x); break;   // exact gelu
            default: v = (x >= 0.f) ? x : LRELU_SLOPE * x; break;
        }
        ov[q] = v * mv[q] * KEEP_SCALE;
    }
    *reinterpret_cast<float4*>(Hout + base + t * 4) =
        make_float4(ov[0], ov[1], ov[2], ov[3]);
    *reinterpret_cast<float4*>(MOut + base + t * 4) = mk;   // fused mask pass-through
}

// ===========================================================================
// Layer 3 + log_softmax: logits = Hm @ W3^T + b3 (C=10), then log_softmax.
// Warp handles 8 rows; W3 fragments hoisted per j-chunk, reused across rows.
// ===========================================================================
__global__ __launch_bounds__(256)
void layer3_kernel(const float* __restrict__ Hm, const float* __restrict__ W3,
                   const float* __restrict__ b3, float* __restrict__ Out)
{
    __shared__ float Ws[C_SZ * H_SZ];
    __shared__ float bs[16];
    for (int i = threadIdx.x; i < C_SZ * H_SZ; i += 256) Ws[i] = W3[i];
    if (threadIdx.x < C_SZ) bs[threadIdx.x] = b3[threadIdx.x];
    __syncthreads();

    const int warp = threadIdx.x >> 5;
    const int lane = threadIdx.x & 31;
    const int row0 = blockIdx.x * 64 + warp * 8;   // 8 rows per warp
    const float4* Ws4 = reinterpret_cast<const float4*>(Ws);

    float acc[8][C_SZ];
#pragma unroll
    for (int r = 0; r < 8; r++)
#pragma unroll
        for (int c = 0; c < C_SZ; c++) acc[r][c] = 0.f;

#pragma unroll
    for (int j = 0; j < 8; j++) {
        int idx = lane + 32 * j;
        float4 wv[C_SZ];
#pragma unroll
        for (int c = 0; c < C_SZ; c++) wv[c] = Ws4[c * 256 + idx];
#pragma unroll
        for (int r = 0; r < 8; r++) {
            float4 hv = *reinterpret_cast<const float4*>(
                &Hm[(size_t)(row0 + r) * H_SZ + idx * 4]);
#pragma unroll
            for (int c = 0; c < C_SZ; c++)
                acc[r][c] += hv.x * wv[c].x + hv.y * wv[c].y
                           + hv.z * wv[c].z + hv.w * wv[c].w;
        }
    }

#pragma unroll
    for (int r = 0; r < 8; r++) {
#pragma unroll
        for (int c = 0; c < C_SZ; c++)
#pragma unroll
            for (int off = 16; off; off >>= 1)
                acc[r][c] += __shfl_xor_sync(0xffffffff, acc[r][c], off);

        if (lane == 0) {
            float l[C_SZ], mx = -INFINITY;
#pragma unroll
            for (int c = 0; c < C_SZ; c++) {
                l[c] = acc[r][c] + bs[c];
                mx = fmaxf(mx, l[c]);
            }
            float s = 0.f;
#pragma unroll
            for (int c = 0; c < C_SZ; c++) s += __expf(l[c] - mx);
            float lse = mx + __logf(s);
#pragma unroll
            for (int c = 0; c < C_SZ; c++)
                Out[(size_t)(row0 + r) * C_SZ + c] = l[c] - lse;
        }
    }
}

// ===========================================================================
extern "C" void kernel_launch(void* const* d_in, const int* in_sizes, int n_in,
                              void* d_out, int out_size)
{
    (void)in_sizes; (void)n_in; (void)out_size;
    const float* x    = (const float*)d_in[0];
    const float* W0   = (const float*)d_in[1];
    const float* b0   = (const float*)d_in[2];
    const float* W1   = (const float*)d_in[3];
    const float* b1   = (const float*)d_in[4];
    const float* W2   = (const float*)d_in[5];
    const float* b2   = (const float*)d_in[6];
    const float* W3   = (const float*)d_in[7];
    const float* b3   = (const float*)d_in[8];
    const float* m1   = (const float*)d_in[9];
    const float* m2   = (const float*)d_in[10];
    const float* m3   = (const float*)d_in[11];
    const int*   tids = (const int*)d_in[12];
    float* out = (float*)d_out;

    float *z, *h;
    cudaGetSymbolAddress((void**)&z, g_z);
    cudaGetSymbolAddress((void**)&h, g_h);

    cudaFuncSetAttribute(gemm_tf32_nt<784>,
                         cudaFuncAttributeMaxDynamicSharedMemorySize, GEMM_SMEM);
    cudaFuncSetAttribute(gemm_tf32_nt<1024>,
                         cudaFuncAttributeMaxDynamicSharedMemorySize, GEMM_SMEM);

    dim3 grid(H_SZ / BN, B_SZ / BM);   // (8, 256)
    float* mout = out + (size_t)B_SZ * C_SZ;
    size_t BH = (size_t)B_SZ * H_SZ;

    gemm_tf32_nt<784><<<grid, 128, GEMM_SMEM>>>(x, W0, b0, z);
    act_kernel<<<B_SZ, 256>>>(z, tids, m1, h, mout);

    gemm_tf32_nt<1024><<<grid, 128, GEMM_SMEM>>>(h, W1, b1, z);
    act_kernel<<<B_SZ, 256>>>(z, tids + H_SZ, m2, h, mout + BH);

    gemm_tf32_nt<1024><<<grid, 128, GEMM_SMEM>>>(h, W2, b2, z);
    act_kernel<<<B_SZ, 256>>>(z, tids + 2 * H_SZ, m3, h, mout + 2 * BH);

    layer3_kernel<<<B_SZ / 64, 256>>>(h, W3, b3, out);
}

// round 10
// speedup vs baseline: 1.1329x; 1.1329x over previous
#include <cuda_runtime.h>
#include <math.h>
#include <stdint.h>

#define B_SZ 32768
#define H_SZ 1024
#define C_SZ 10
#define KEEP_SCALE 2.0f
#define LRELU_SLOPE 0.01f

// Scratch (device globals — allocation is forbidden)
__device__ float g_z[(size_t)B_SZ * H_SZ];   // pre-activation
__device__ float g_h[(size_t)B_SZ * H_SZ];   // activation * mask * 2

// ===========================================================================
// Helpers
// ===========================================================================
__device__ __forceinline__ uint32_t smem_u32(const void* p) {
    uint32_t a;
    asm("{ .reg .u64 t; cvta.to.shared.u64 t, %1; cvt.u32.u64 %0, t; }"
        : "=r"(a) : "l"(p));
    return a;
}

__device__ __forceinline__ void cp_async16(uint32_t dst, const void* src, int src_bytes) {
    asm volatile("cp.async.cg.shared.global [%0], [%1], 16, %2;"
                 :: "r"(dst), "l"(src), "r"(src_bytes) : "memory");
}

__device__ __forceinline__ float tanh_fast(float x) {
    float r;
    asm("tanh.approx.f32 %0, %1;" : "=f"(r) : "f"(x));
    return r;
}

__device__ __forceinline__ void mma_tf32(float* d, const uint32_t* a, const uint32_t* b) {
    asm volatile(
        "mma.sync.aligned.m16n8k8.row.col.f32.tf32.tf32.f32 "
        "{%0,%1,%2,%3}, {%4,%5,%6,%7}, {%8,%9}, {%0,%1,%2,%3};"
        : "+f"(d[0]), "+f"(d[1]), "+f"(d[2]), "+f"(d[3])
        : "r"(a[0]), "r"(a[1]), "r"(a[2]), "r"(a[3]), "r"(b[0]), "r"(b[1]));
}

// ===========================================================================
// tf32 mma.sync GEMM (validated R6 config): Z[m,n] = sum_k A[m,k]*W[n,k]+bias[n]
// CTA 128x256, BK=32, 256 threads (8 warps 2x4, warp tile 64x64).
// Smem m-major [row][36]; tf32 fed as raw fp32 bits (HW truncates).
// 4-stage cp.async pipeline with zfill for K tail.
// ===========================================================================
#define BM 128
#define BN 256
#define BK 32
#define PAD 36
#define NSTAGE 4
#define STG_FLOATS ((BM + BN) * PAD)            // 13824 floats
#define GEMM_SMEM (NSTAGE * STG_FLOATS * 4)     // 221184 bytes

template <int K>
__global__ __launch_bounds__(256, 1)
void gemm_tf32_nt(const float* __restrict__ A, const float* __restrict__ W,
                  const float* __restrict__ bias, float* __restrict__ Z)
{
    constexpr int NK = (K + BK - 1) / BK;

    extern __shared__ __align__(16) float sm[];

    const int tid  = threadIdx.x;
    const int wid  = tid >> 5;
    const int lane = tid & 31;
    const int g    = lane >> 2;   // groupID (0..7)
    const int tig  = lane & 3;    // thread-in-group (0..3)
    const int warpM = (wid & 1) * 64;       // 2 warp-rows
    const int warpN = (wid >> 1) * 64;      // 4 warp-cols
    const int bm = blockIdx.y * BM;
    const int bn = blockIdx.x * BN;

    const float* Ag = A + (size_t)bm * K;
    const float* Wg = W + (size_t)bn * K;

    float acc[4][8][4];
#pragma unroll
    for (int i = 0; i < 4; i++)
#pragma unroll
        for (int j = 0; j < 8; j++)
#pragma unroll
            for (int q = 0; q < 4; q++) acc[i][j][q] = 0.f;

    auto load_stage = [&](int s, int kc) {
        const int k0 = kc * BK;
        float* As = sm + s * STG_FLOATS;
        float* Bs = As + BM * PAD;
        // A: 128 rows x 8 quads(16B) = 1024 granules
#pragma unroll
        for (int it = 0; it < 4; it++) {
            int idx = tid + it * 256;
            int row = idx >> 3, q = idx & 7;
            int gk  = k0 + q * 4;
            int sb  = (K % BK == 0) ? 16 : ((gk < K) ? 16 : 0);
            int gkc = (K % BK == 0) ? gk : min(gk, K - 4);
            cp_async16(smem_u32(&As[row * PAD + q * 4]),
                       Ag + (size_t)row * K + gkc, sb);
        }
        // B: 256 rows x 8 quads = 2048 granules
#pragma unroll
        for (int it = 0; it < 8; it++) {
            int idx = tid + it * 256;
            int row = idx >> 3, q = idx & 7;
            int gk  = k0 + q * 4;
            int sb  = (K % BK == 0) ? 16 : ((gk < K) ? 16 : 0);
            int gkc = (K % BK == 0) ? gk : min(gk, K - 4);
            cp_async16(smem_u32(&Bs[row * PAD + q * 4]),
                       Wg + (size_t)row * K + gkc, sb);
        }
    };

    // Prologue
#pragma unroll
    for (int s = 0; s < NSTAGE - 1; s++) {
        load_stage(s, s);
        asm volatile("cp.async.commit_group;" ::: "memory");
    }

#pragma unroll 1
    for (int ki = 0; ki < NK; ki++) {
        asm volatile("cp.async.wait_group 2;" ::: "memory");
        __syncthreads();

        const float* As = sm + (ki & 3) * STG_FLOATS;
        const float* Bs = As + BM * PAD;

#pragma unroll
        for (int ks = 0; ks < 4; ks++) {
            const int kb = 8 * ks + tig;

            uint32_t af[4][4];
#pragma unroll
            for (int i = 0; i < 4; i++) {
                int base = (warpM + 16 * i + g) * PAD + kb;
                af[i][0] = __float_as_uint(As[base]);
                af[i][1] = __float_as_uint(As[base + 8 * PAD]);
                af[i][2] = __float_as_uint(As[base + 4]);
                af[i][3] = __float_as_uint(As[base + 8 * PAD + 4]);
            }
            uint32_t bf[8][2];
#pragma unroll
            for (int j = 0; j < 8; j++) {
                int base = (warpN + 8 * j + g) * PAD + kb;
                bf[j][0] = __float_as_uint(Bs[base]);
                bf[j][1] = __float_as_uint(Bs[base + 4]);
            }
#pragma unroll
            for (int i = 0; i < 4; i++)
#pragma unroll
                for (int j = 0; j < 8; j++)
                    mma_tf32(acc[i][j], af[i], bf[j]);
        }

        const int kn = ki + NSTAGE - 1;
        if (kn < NK) load_stage(kn & 3, kn);
        asm volatile("cp.async.commit_group;" ::: "memory");
    }

    // Epilogue: bias + store
#pragma unroll
    for (int i = 0; i < 4; i++) {
        int row0 = bm + warpM + 16 * i + g;
#pragma unroll
        for (int j = 0; j < 8; j++) {
            int col = bn + warpN + 8 * j + 2 * tig;
            float2 bi = *reinterpret_cast<const float2*>(&bias[col]);
            float2 v0 = make_float2(acc[i][j][0] + bi.x, acc[i][j][1] + bi.y);
            float2 v1 = make_float2(acc[i][j][2] + bi.x, acc[i][j][3] + bi.y);
            *reinterpret_cast<float2*>(&Z[(size_t)row0 * H_SZ + col]) = v0;
            *reinterpret_cast<float2*>(&Z[(size_t)(row0 + 8) * H_SZ + col]) = v1;
        }
    }
}

// ===========================================================================
// Mixed activation v4: E cached from reduction phase; relu/lrelu merged;
// tanh & sigmoid share one tanh.approx; only gelu branches (exact normcdff).
// Softmax/softmin without max-subtraction (|z| small). Fused mask pass-through.
// ===========================================================================
__global__ __launch_bounds__(256)
void act_kernel(const float* __restrict__ Z, const int* __restrict__ tids,
                const float* __restrict__ mask, float* __restrict__ Hout,
                float* __restrict__ MOut)
{
    const int row  = blockIdx.x;
    const int t    = threadIdx.x;
    const int lane = t & 31, wid = t >> 5;
    const size_t base = (size_t)row * H_SZ;

    float4 z4 = *reinterpret_cast<const float4*>(Z + base + t * 4);
    int4  i4 = *reinterpret_cast<const int4*>(tids + t * 4);
    float zr[4] = {z4.x, z4.y, z4.z, z4.w};
    int   tr[4] = {i4.x, i4.y, i4.z, i4.w};

    // Phase 1: exp for softmax/softmin lanes (cache E), reduce sums.
    float E[4];
    float s3 = 0.f, s4 = 0.f;
#pragma unroll
    for (int q = 0; q < 4; q++) {
        bool p3 = (tr[q] == 3), p4 = (tr[q] == 4);
        float sg = p4 ? -zr[q] : zr[q];
        E[q] = __expf(sg);                    // valid for p3/p4 lanes
        s3 += p3 ? E[q] : 0.f;
        s4 += p4 ? E[q] : 0.f;
    }
#pragma unroll
    for (int off = 16; off; off >>= 1) {
        s3 += __shfl_xor_sync(0xffffffffu, s3, off);
        s4 += __shfl_xor_sync(0xffffffffu, s4, off);
    }
    __shared__ float sC[8], sD[8];
    if (lane == 0) { sC[wid] = s3; sD[wid] = s4; }
    __syncthreads();
    s3 = 0.f; s4 = 0.f;
#pragma unroll
    for (int j = 0; j < 8; j++) { s3 += sC[j]; s4 += sD[j]; }
    float r3 = __frcp_rn(s3), r4 = __frcp_rn(s4);

    float4 mk = *reinterpret_cast<const float4*>(mask + base + t * 4);
    float mv[4] = {mk.x, mk.y, mk.z, mk.w};
    float ov[4];
#pragma unroll
    for (int q = 0; q < 4; q++) {
        float x = zr[q];
        int  ty = tr[q];
        // relu (0) / lrelu (6) merged
        float cmin  = (ty == 6) ? LRELU_SLOPE : 0.f;
        float vrelu = fmaxf(x, 0.f) + cmin * fminf(x, 0.f);
        // tanh (1) / sigmoid (2) share one MUFU: sig(x) = 0.5*tanh(x/2)+0.5
        float targ  = (ty == 2) ? 0.5f * x : x;
        float th    = tanh_fast(targ);
        float vtanh = (ty == 2) ? fmaf(0.5f, th, 0.5f) : th;
        // softmax (3) / softmin (4) reuse cached E
        float vsoft = E[q] * ((ty == 3) ? r3 : r4);
        float v = (ty <= 0) ? vrelu
                : (ty <= 2) ? vtanh
                : (ty <= 4) ? vsoft
                : vrelu;                       // ty==6 lands here too
        if (ty == 5) v = x * normcdff(x);      // exact gelu, lone branch
        ov[q] = v * mv[q] * KEEP_SCALE;
    }
    *reinterpret_cast<float4*>(Hout + base + t * 4) =
        make_float4(ov[0], ov[1], ov[2], ov[3]);
    *reinterpret_cast<float4*>(MOut + base + t * 4) = mk;   // fused mask pass-through
}

// ===========================================================================
// Layer 3 + log_softmax: logits = Hm @ W3^T + b3 (C=10), then log_softmax.
// Warp handles 8 rows; W3 fragments hoisted per j-chunk, reused across rows.
// ===========================================================================
__global__ __launch_bounds__(256)
void layer3_kernel(const float* __restrict__ Hm, const float* __restrict__ W3,
                   const float* __restrict__ b3, float* __restrict__ Out)
{
    __shared__ float Ws[C_SZ * H_SZ];
    __shared__ float bs[16];
    for (int i = threadIdx.x; i < C_SZ * H_SZ; i += 256) Ws[i] = W3[i];
    if (threadIdx.x < C_SZ) bs[threadIdx.x] = b3[threadIdx.x];
    __syncthreads();

    const int warp = threadIdx.x >> 5;
    const int lane = threadIdx.x & 31;
    const int row0 = blockIdx.x * 64 + warp * 8;   // 8 rows per warp
    const float4* Ws4 = reinterpret_cast<const float4*>(Ws);

    float acc[8][C_SZ];
#pragma unroll
    for (int r = 0; r < 8; r++)
#pragma unroll
        for (int c = 0; c < C_SZ; c++) acc[r][c] = 0.f;

#pragma unroll
    for (int j = 0; j < 8; j++) {
        int idx = lane + 32 * j;
        float4 wv[C_SZ];
#pragma unroll
        for (int c = 0; c < C_SZ; c++) wv[c] = Ws4[c * 256 + idx];
#pragma unroll
        for (int r = 0; r < 8; r++) {
            float4 hv = *reinterpret_cast<const float4*>(
                &Hm[(size_t)(row0 + r) * H_SZ + idx * 4]);
#pragma unroll
            for (int c = 0; c < C_SZ; c++)
                acc[r][c] += hv.x * wv[c].x + hv.y * wv[c].y
                           + hv.z * wv[c].z + hv.w * wv[c].w;
        }
    }

#pragma unroll
    for (int r = 0; r < 8; r++) {
#pragma unroll
        for (int c = 0; c < C_SZ; c++)
#pragma unroll
            for (int off = 16; off; off >>= 1)
                acc[r][c] += __shfl_xor_sync(0xffffffff, acc[r][c], off);

        if (lane == 0) {
            float l[C_SZ], mx = -INFINITY;
#pragma unroll
            for (int c = 0; c < C_SZ; c++) {
                l[c] = acc[r][c] + bs[c];
                mx = fmaxf(mx, l[c]);
            }
            float s = 0.f;
#pragma unroll
            for (int c = 0; c < C_SZ; c++) s += __expf(l[c] - mx);
            float lse = mx + __logf(s);
#pragma unroll
            for (int c = 0; c < C_SZ; c++)
                Out[(size_t)(row0 + r) * C_SZ + c] = l[c] - lse;
        }
    }
}

// ===========================================================================
extern "C" void kernel_launch(void* const* d_in, const int* in_sizes, int n_in,
                              void* d_out, int out_size)
{
    (void)in_sizes; (void)n_in; (void)out_size;
    const float* x    = (const float*)d_in[0];
    const float* W0   = (const float*)d_in[1];
    const float* b0   = (const float*)d_in[2];
    const float* W1   = (const float*)d_in[3];
    const float* b1   = (const float*)d_in[4];
    const float* W2   = (const float*)d_in[5];
    const float* b2   = (const float*)d_in[6];
    const float* W3   = (const float*)d_in[7];
    const float* b3   = (const float*)d_in[8];
    const float* m1   = (const float*)d_in[9];
    const float* m2   = (const float*)d_in[10];
    const float* m3   = (const float*)d_in[11];
    const int*   tids = (const int*)d_in[12];
    float* out = (float*)d_out;

    float *z, *h;
    cudaGetSymbolAddress((void**)&z, g_z);
    cudaGetSymbolAddress((void**)&h, g_h);

    cudaFuncSetAttribute(gemm_tf32_nt<784>,
                         cudaFuncAttributeMaxDynamicSharedMemorySize, GEMM_SMEM);
    cudaFuncSetAttribute(gemm_tf32_nt<1024>,
                         cudaFuncAttributeMaxDynamicSharedMemorySize, GEMM_SMEM);

    dim3 grid(H_SZ / BN, B_SZ / BM);   // (4, 256)
    float* mout = out + (size_t)B_SZ * C_SZ;
    size_t BH = (size_t)B_SZ * H_SZ;

    gemm_tf32_nt<784><<<grid, 256, GEMM_SMEM>>>(x, W0, b0, z);
    act_kernel<<<B_SZ, 256>>>(z, tids, m1, h, mout);

    gemm_tf32_nt<1024><<<grid, 256, GEMM_SMEM>>>(h, W1, b1, z);
    act_kernel<<<B_SZ, 256>>>(z, tids + H_SZ, m2, h, mout + BH);

    gemm_tf32_nt<1024><<<grid, 256, GEMM_SMEM>>>(h, W2, b2, z);
    act_kernel<<<B_SZ, 256>>>(z, tids + 2 * H_SZ, m3, h, mout + 2 * BH);

    layer3_kernel<<<B_SZ / 64, 256>>>(h, W3, b3, out);
}